// round 2
// baseline (speedup 1.0000x reference)
#include <cuda_runtime.h>
#include <cstdint>

#define NN 65536
#define NE (NN*16)
#define NG 128
#define PN 512
#define HIDD 128
#define INDIM 64
#define BN_EPS 1e-5f

// ---------------- scratch (device globals; no allocation allowed) ----------------
__device__ int   g_count[NN];
__device__ int   g_rowptr[NN+1];
__device__ int   g_cursor[NN];
__device__ int   g_esrc[NE];
__device__ float g_ew[NE];
__device__ float g_dis[NN];
__device__ float g_selfn[NN];
__device__ float g_h[(size_t)NN*HIDD];
__device__ float g_agg[(size_t)NN*HIDD];
__device__ float g_qkv[(size_t)NN*3*HIDD];
__device__ float g_attno[(size_t)NN*HIDD];

// ---------------- CSR build ----------------
__global__ void zero_count_kernel(){
  int n = blockIdx.x*blockDim.x + threadIdx.x;
  if(n < NN) g_count[n] = 0;
}
__global__ void count_kernel(const int* __restrict__ dst){
  int e = blockIdx.x*blockDim.x + threadIdx.x;
  if(e < NE) atomicAdd(&g_count[dst[e]], 1);
}
__global__ void deg_kernel(){
  int n = blockIdx.x*blockDim.x + threadIdx.x;
  if(n >= NN) return;
  float dis = rsqrtf((float)(g_count[n] + 1));
  g_dis[n] = dis;
  g_selfn[n] = dis*dis;
}
__global__ void scan_kernel(){
  __shared__ int part[1024];
  int t = threadIdx.x;
  int base = t*64;
  int s = 0;
  #pragma unroll 8
  for(int i=0;i<64;i++) s += g_count[base+i];
  part[t] = s;
  __syncthreads();
  for(int off=1; off<1024; off<<=1){
    int v = 0;
    if(t >= off) v = part[t-off];
    __syncthreads();
    if(t >= off) part[t] += v;
    __syncthreads();
  }
  int run = (t==0) ? 0 : part[t-1];
  for(int i=0;i<64;i++){
    int c = g_count[base+i];
    g_rowptr[base+i] = run;
    g_cursor[base+i] = run;
    run += c;
  }
  if(t == 1023) g_rowptr[NN] = run;
}
__global__ void fill_kernel(const int* __restrict__ src, const int* __restrict__ dst){
  int e = blockIdx.x*blockDim.x + threadIdx.x;
  if(e >= NE) return;
  int s = src[e], d = dst[e];
  int pos = atomicAdd(&g_cursor[d], 1);
  g_esrc[pos] = s;
  g_ew[pos] = g_dis[s]*g_dis[d];
}

// ---------------- aggregation (warp per node, gather-only) ----------------
__global__ void agg64_kernel(const float* __restrict__ hin, float* __restrict__ out){
  int gw = (blockIdx.x*blockDim.x + threadIdx.x) >> 5;
  int lane = threadIdx.x & 31;
  if(gw >= NN) return;
  float2 a = *((const float2*)(hin + (size_t)gw*INDIM) + lane);
  float sn = g_selfn[gw];
  a.x *= sn; a.y *= sn;
  int beg = g_rowptr[gw], end = g_rowptr[gw+1];
  for(int e = beg; e < end; e++){
    int s = g_esrc[e];
    float w = g_ew[e];
    float2 v = *((const float2*)(hin + (size_t)s*INDIM) + lane);
    a.x += w*v.x; a.y += w*v.y;
  }
  *((float2*)(out + (size_t)gw*INDIM) + lane) = a;
}
__global__ void agg128_kernel(const float* __restrict__ hin, float* __restrict__ out){
  int gw = (blockIdx.x*blockDim.x + threadIdx.x) >> 5;
  int lane = threadIdx.x & 31;
  if(gw >= NN) return;
  float4 a = *((const float4*)(hin + (size_t)gw*HIDD) + lane);
  float sn = g_selfn[gw];
  a.x *= sn; a.y *= sn; a.z *= sn; a.w *= sn;
  int beg = g_rowptr[gw], end = g_rowptr[gw+1];
  for(int e = beg; e < end; e++){
    int s = g_esrc[e];
    float w = g_ew[e];
    float4 v = *((const float4*)(hin + (size_t)s*HIDD) + lane);
    a.x += w*v.x; a.y += w*v.y; a.z += w*v.z; a.w += w*v.w;
  }
  *((float4*)(out + (size_t)gw*HIDD) + lane) = a;
}

// ---------------- GEMM: C[M x Ndt tile] = A[M x K] * B (+bias, optional BN+ReLU) ----
// BT=0: B is [K][Ndt] row-major (h @ W). BT=1: B is [Ncols][K] (x @ W^T).
// Full K staged in smem: Ast[K][128] (A transposed), Bs[K][128].
template<int BT, int EPI>
__global__ __launch_bounds__(256)
void gemm_kernel(const float* __restrict__ A, const float* __restrict__ B,
                 const float* __restrict__ bias,
                 const float* __restrict__ bng, const float* __restrict__ bnb,
                 const float* __restrict__ bnm, const float* __restrict__ bnv,
                 float* __restrict__ C, int K, int Ndt)
{
  extern __shared__ float sm[];
  float* Ast = sm;          // [K][128]
  float* Bs  = sm + K*128;  // [K][128]
  int row0 = blockIdx.y * 128;
  int col0 = blockIdx.x * 128;
  int t = threadIdx.x;
  int kq4 = K >> 2;

  // load A tile, transposed into Ast[k][r]
  for(int idx = t; idx < 128*kq4; idx += 256){
    int r = idx / kq4, kq = idx % kq4;
    float4 v = *(const float4*)(A + (size_t)(row0 + r)*K + kq*4);
    Ast[(kq*4+0)*128 + r] = v.x;
    Ast[(kq*4+1)*128 + r] = v.y;
    Ast[(kq*4+2)*128 + r] = v.z;
    Ast[(kq*4+3)*128 + r] = v.w;
  }
  // load B tile into Bs[k][c]
  if(BT){
    for(int idx = t; idx < 128*kq4; idx += 256){
      int c = idx / kq4, kq = idx % kq4;
      float4 v = *(const float4*)(B + (size_t)(col0 + c)*K + kq*4);
      Bs[(kq*4+0)*128 + c] = v.x;
      Bs[(kq*4+1)*128 + c] = v.y;
      Bs[(kq*4+2)*128 + c] = v.z;
      Bs[(kq*4+3)*128 + c] = v.w;
    }
  } else {
    for(int idx = t; idx < K*32; idx += 256){
      int k = idx >> 5, cq = idx & 31;
      *(float4*)(Bs + k*128 + cq*4) =
        *(const float4*)(B + (size_t)k*Ndt + col0 + cq*4);
    }
  }
  __syncthreads();

  int ty = t >> 4, tx = t & 15;   // 16x16 threads, 8x8 outputs each
  float acc[8][8];
  #pragma unroll
  for(int i=0;i<8;i++)
    #pragma unroll
    for(int j=0;j<8;j++) acc[i][j] = 0.f;

  for(int k = 0; k < K; k++){
    float4 a0 = *(const float4*)(Ast + k*128 + ty*8);
    float4 a1 = *(const float4*)(Ast + k*128 + ty*8 + 4);
    float4 b0 = *(const float4*)(Bs  + k*128 + tx*8);
    float4 b1 = *(const float4*)(Bs  + k*128 + tx*8 + 4);
    float av[8] = {a0.x,a0.y,a0.z,a0.w,a1.x,a1.y,a1.z,a1.w};
    float bv[8] = {b0.x,b0.y,b0.z,b0.w,b1.x,b1.y,b1.z,b1.w};
    #pragma unroll
    for(int i=0;i<8;i++)
      #pragma unroll
      for(int j=0;j<8;j++) acc[i][j] += av[i]*bv[j];
  }

  #pragma unroll
  for(int i=0;i<8;i++){
    int r = row0 + ty*8 + i;
    #pragma unroll
    for(int jq=0;jq<2;jq++){
      float4 o;
      #pragma unroll
      for(int j=0;j<4;j++){
        int c = col0 + tx*8 + jq*4 + j;
        float v = acc[i][jq*4+j] + bias[c];
        if(EPI){
          float sc = bng[c]*rsqrtf(bnv[c] + BN_EPS);
          v = (v - bnm[c])*sc + bnb[c];
          v = fmaxf(v, 0.f);
        }
        (&o.x)[j] = v;
      }
      *(float4*)(C + (size_t)r*Ndt + col0 + tx*8 + jq*4) = o;
    }
  }
}

// ---------------- attention: CTA per (graph, head) ----------------
// smem: Ks[512][33] | Vs[512][32] | Qs[32][32] | S[32][516]
__global__ __launch_bounds__(256)
void attn_kernel(const float* __restrict__ qkv, float* __restrict__ out){
  extern __shared__ float sm[];
  float* Ks = sm;                   // 512*33
  float* Vs = Ks + 512*33;          // 512*32
  float* Qs = Vs + 512*32;          // 32*32
  float* S  = Qs + 32*32;           // 32*516
  int g  = blockIdx.x >> 2;
  int hd = blockIdx.x & 3;
  int n0 = g*PN;
  int t = threadIdx.x;
  int lane = t & 31, warp = t >> 5;
  const float scale = 0.17677669529663687f;  // 1/sqrt(32)

  for(int idx = t; idx < PN*32; idx += 256){
    int r = idx >> 5, d = idx & 31;
    const float* row = qkv + (size_t)(n0 + r)*384 + hd*32;
    Ks[r*33 + d] = row[128 + d];
    Vs[r*32 + d] = row[256 + d];
  }
  __syncthreads();

  for(int qt = 0; qt < 16; qt++){
    // Q tile
    for(int idx = t; idx < 32*32; idx += 256){
      int r = idx >> 5, d = idx & 31;
      Qs[r*32 + d] = qkv[(size_t)(n0 + qt*32 + r)*384 + hd*32 + d];
    }
    __syncthreads();

    // Phase A: S = Q K^T * scale   (warp handles 4 q-rows; lane x 4 interleaved keys)
    for(int kb = 0; kb < 4; kb++){
      float acc00=0,acc01=0,acc02=0,acc03=0;
      float acc10=0,acc11=0,acc12=0,acc13=0;
      float acc20=0,acc21=0,acc22=0,acc23=0;
      float acc30=0,acc31=0,acc32=0,acc33=0;
      #pragma unroll 8
      for(int d = 0; d < 32; d++){
        float q0 = Qs[(warp*4+0)*32 + d];
        float q1 = Qs[(warp*4+1)*32 + d];
        float q2 = Qs[(warp*4+2)*32 + d];
        float q3 = Qs[(warp*4+3)*32 + d];
        float k0 = Ks[(kb*128 +  0 + lane)*33 + d];
        float k1 = Ks[(kb*128 + 32 + lane)*33 + d];
        float k2 = Ks[(kb*128 + 64 + lane)*33 + d];
        float k3 = Ks[(kb*128 + 96 + lane)*33 + d];
        acc00 += q0*k0; acc01 += q0*k1; acc02 += q0*k2; acc03 += q0*k3;
        acc10 += q1*k0; acc11 += q1*k1; acc12 += q1*k2; acc13 += q1*k3;
        acc20 += q2*k0; acc21 += q2*k1; acc22 += q2*k2; acc23 += q2*k3;
        acc30 += q3*k0; acc31 += q3*k1; acc32 += q3*k2; acc33 += q3*k3;
      }
      S[(warp*4+0)*516 + kb*128 +  0 + lane] = acc00*scale;
      S[(warp*4+0)*516 + kb*128 + 32 + lane] = acc01*scale;
      S[(warp*4+0)*516 + kb*128 + 64 + lane] = acc02*scale;
      S[(warp*4+0)*516 + kb*128 + 96 + lane] = acc03*scale;
      S[(warp*4+1)*516 + kb*128 +  0 + lane] = acc10*scale;
      S[(warp*4+1)*516 + kb*128 + 32 + lane] = acc11*scale;
      S[(warp*4+1)*516 + kb*128 + 64 + lane] = acc12*scale;
      S[(warp*4+1)*516 + kb*128 + 96 + lane] = acc13*scale;
      S[(warp*4+2)*516 + kb*128 +  0 + lane] = acc20*scale;
      S[(warp*4+2)*516 + kb*128 + 32 + lane] = acc21*scale;
      S[(warp*4+2)*516 + kb*128 + 64 + lane] = acc22*scale;
      S[(warp*4+2)*516 + kb*128 + 96 + lane] = acc23*scale;
      S[(warp*4+3)*516 + kb*128 +  0 + lane] = acc30*scale;
      S[(warp*4+3)*516 + kb*128 + 32 + lane] = acc31*scale;
      S[(warp*4+3)*516 + kb*128 + 64 + lane] = acc32*scale;
      S[(warp*4+3)*516 + kb*128 + 96 + lane] = acc33*scale;
    }
    __syncthreads();

    // Phase B: row softmax (warp per row, 4 rows/warp)
    for(int rr = 0; rr < 4; rr++){
      int r = warp*4 + rr;
      float mx = -1e30f;
      for(int j = lane; j < 512; j += 32) mx = fmaxf(mx, S[r*516 + j]);
      #pragma unroll
      for(int o=16;o;o>>=1) mx = fmaxf(mx, __shfl_xor_sync(0xffffffffu, mx, o));
      float sum = 0.f;
      for(int j = lane; j < 512; j += 32){
        float e = __expf(S[r*516 + j] - mx);
        S[r*516 + j] = e;
        sum += e;
      }
      #pragma unroll
      for(int o=16;o;o>>=1) sum += __shfl_xor_sync(0xffffffffu, sum, o);
      float inv = 1.f/sum;
      for(int j = lane; j < 512; j += 32) S[r*516 + j] *= inv;
    }
    __syncthreads();

    // Phase C: O = P V   (thread: 1 query row x 4 output dims)
    {
      int qi = t >> 3;
      int dbase = (t & 7)*4;
      float o0=0,o1=0,o2=0,o3=0;
      const float* Srow = S + qi*516;
      #pragma unroll 8
      for(int j = 0; j < 512; j++){
        float p = Srow[j];
        float4 v = *(const float4*)(Vs + j*32 + dbase);
        o0 += p*v.x; o1 += p*v.y; o2 += p*v.z; o3 += p*v.w;
      }
      int n = n0 + qt*32 + qi;
      float4* op = (float4*)(out + (size_t)n*HIDD + hd*32 + dbase);
      *op = make_float4(o0,o1,o2,o3);
    }
    __syncthreads();
  }
}

// ---------------- mean pool ----------------
__global__ void pool_kernel(const float* __restrict__ fin, float* __restrict__ emb){
  int g = blockIdx.x, d = threadIdx.x;
  float s = 0.f;
  const float* base = fin + (size_t)g*PN*HIDD + d;
  for(int i = 0; i < PN; i++) s += base[(size_t)i*HIDD];
  emb[g*HIDD + d] = s * (1.0f/PN);
}

// ---------------- launch ----------------
extern "C" void kernel_launch(void* const* d_in, const int* in_sizes, int n_in,
                              void* d_out, int out_size) {
  const float* x   = (const float*)d_in[0];
  const float* W0  = (const float*)d_in[1];
  const float* b0  = (const float*)d_in[2];
  const float* Wh  = (const float*)d_in[3];
  const float* bh  = (const float*)d_in[4];
  const float* bng = (const float*)d_in[5];
  const float* bnb = (const float*)d_in[6];
  const float* bnm = (const float*)d_in[7];
  const float* bnv = (const float*)d_in[8];
  const float* aiw = (const float*)d_in[9];
  const float* aib = (const float*)d_in[10];
  const float* aow = (const float*)d_in[11];
  const float* aob = (const float*)d_in[12];
  const int*  eidx = (const int*)d_in[13];
  // d_in[14] = batch (contiguous equal-size graphs; implicit)

  float* out_final = (float*)d_out;
  float* out_emb   = out_final + (size_t)NN*HIDD;

  const int* src = eidx;
  const int* dst = eidx + NE;

  float *p_h, *p_agg, *p_qkv, *p_attno;
  cudaGetSymbolAddress((void**)&p_h,     g_h);
  cudaGetSymbolAddress((void**)&p_agg,   g_agg);
  cudaGetSymbolAddress((void**)&p_qkv,   g_qkv);
  cudaGetSymbolAddress((void**)&p_attno, g_attno);

  cudaFuncSetAttribute(gemm_kernel<0,1>, cudaFuncAttributeMaxDynamicSharedMemorySize, 131072);
  cudaFuncSetAttribute(gemm_kernel<1,0>, cudaFuncAttributeMaxDynamicSharedMemorySize, 131072);
  cudaFuncSetAttribute(attn_kernel,      cudaFuncAttributeMaxDynamicSharedMemorySize, 203264);

  // CSR build
  zero_count_kernel<<<NN/256, 256>>>();
  count_kernel<<<NE/256, 256>>>(dst);
  deg_kernel<<<NN/256, 256>>>();
  scan_kernel<<<1, 1024>>>();
  fill_kernel<<<NE/256, 256>>>(src, dst);

  // layer 0: aggregate in input space (64-d), then GEMM + BN + ReLU
  agg64_kernel<<<NN*32/256, 256>>>(x, p_agg);
  gemm_kernel<0,1><<<dim3(1,512), 256, 64*256*4>>>(
      p_agg, W0, b0, bng, bnb, bnm, bnv, p_h, 64, 128);

  // layers 1..3
  for(int l = 0; l < 3; l++){
    agg128_kernel<<<NN*32/256, 256>>>(p_h, p_agg);
    gemm_kernel<0,1><<<dim3(1,512), 256, 128*256*4>>>(
        p_agg, Wh + (size_t)l*HIDD*HIDD, bh + l*HIDD,
        bng + (l+1)*HIDD, bnb + (l+1)*HIDD, bnm + (l+1)*HIDD, bnv + (l+1)*HIDD,
        p_h, 128, 128);
  }

  // qkv projection: [N,128] @ attn_in_w^T -> [N,384]
  gemm_kernel<1,0><<<dim3(3,512), 256, 131072>>>(
      p_h, aiw, aib, nullptr, nullptr, nullptr, nullptr, p_qkv, 128, 384);

  // attention per (graph, head)
  attn_kernel<<<NG*4, 256, 203264>>>(p_qkv, p_attno);

  // output projection -> final (directly into d_out)
  gemm_kernel<1,0><<<dim3(1,512), 256, 131072>>>(
      p_attno, aow, aob, nullptr, nullptr, nullptr, nullptr, out_final, 128, 128);

  // mean pool -> graph_emb
  pool_kernel<<<NG, HIDD>>>(out_final, out_emb);
}